// round 3
// baseline (speedup 1.0000x reference)
#include <cuda_runtime.h>
#include <math.h>

#define BSZ    2
#define NSEQ   2048
#define DMODEL 1024
#define NHEAD  16
#define DKH    64
#define MROWS  (BSZ * NSEQ)     // 4096

// Scratch (allocation-free rule: __device__ globals)
__device__ float g_q[BSZ * NSEQ * DMODEL];
__device__ float g_k[BSZ * NSEQ * DMODEL];
__device__ float g_v[BSZ * NSEQ * DMODEL];
__device__ float g_o[BSZ * NSEQ * DMODEL];

// ---------------------------------------------------------------------------
// SGEMM (NT): C[m][n] = sum_k A[m][k] * W[n][k] + bias[n]
// A: [M,K] row-major, W: [N,K] row-major. M,N multiples of 128; K multiple of 16.
// 128x128 tile, K-step 16, 256 threads, 8x8 per thread.
// ---------------------------------------------------------------------------
__global__ __launch_bounds__(256) void sgemm_nt_bias(
    const float* __restrict__ A, const float* __restrict__ W,
    const float* __restrict__ bias, float* __restrict__ C,
    int M, int N, int K)
{
    __shared__ float As[16][132];   // As[k][m] (transposed stage)
    __shared__ float Ws[16][132];   // Ws[k][n]

    const int tid = threadIdx.x;
    const int m0 = blockIdx.y * 128;
    const int n0 = blockIdx.x * 128;
    const int ty = tid >> 4;        // 0..15 -> rows ty*8..+7
    const int tx = tid & 15;        // 0..15 -> cols tx*8..+7

    float acc[8][8];
#pragma unroll
    for (int i = 0; i < 8; ++i)
#pragma unroll
        for (int j = 0; j < 8; ++j) acc[i][j] = 0.f;

    for (int kt = 0; kt < K; kt += 16) {
        // global -> regs (issued before sync to overlap with prior compute)
        float4 av[2], wv[2];
#pragma unroll
        for (int i = 0; i < 2; ++i) {
            int idx = tid + i * 256;          // 0..511
            int row = idx >> 2;               // 0..127
            int kg  = (idx & 3) << 2;         // 0,4,8,12
            av[i] = *(const float4*)&A[(size_t)(m0 + row) * K + kt + kg];
            wv[i] = *(const float4*)&W[(size_t)(n0 + row) * K + kt + kg];
        }
        __syncthreads();   // prior compute done before overwriting smem
#pragma unroll
        for (int i = 0; i < 2; ++i) {
            int idx = tid + i * 256;
            int row = idx >> 2;
            int kg  = (idx & 3) << 2;
            As[kg + 0][row] = av[i].x; As[kg + 1][row] = av[i].y;
            As[kg + 2][row] = av[i].z; As[kg + 3][row] = av[i].w;
            Ws[kg + 0][row] = wv[i].x; Ws[kg + 1][row] = wv[i].y;
            Ws[kg + 2][row] = wv[i].z; Ws[kg + 3][row] = wv[i].w;
        }
        __syncthreads();

#pragma unroll
        for (int kk = 0; kk < 16; ++kk) {
            float4 a0 = *(const float4*)&As[kk][ty * 8];
            float4 a1 = *(const float4*)&As[kk][ty * 8 + 4];
            float4 b0 = *(const float4*)&Ws[kk][tx * 8];
            float4 b1 = *(const float4*)&Ws[kk][tx * 8 + 4];
            float ar[8] = {a0.x, a0.y, a0.z, a0.w, a1.x, a1.y, a1.z, a1.w};
            float br[8] = {b0.x, b0.y, b0.z, b0.w, b1.x, b1.y, b1.z, b1.w};
#pragma unroll
            for (int i = 0; i < 8; ++i)
#pragma unroll
                for (int j = 0; j < 8; ++j)
                    acc[i][j] = fmaf(ar[i], br[j], acc[i][j]);
        }
    }

    float bj[8];
#pragma unroll
    for (int j = 0; j < 8; ++j) bj[j] = bias[n0 + tx * 8 + j];

#pragma unroll
    for (int i = 0; i < 8; ++i) {
        int m = m0 + ty * 8 + i;
        float4 o0, o1;
        o0.x = acc[i][0] + bj[0]; o0.y = acc[i][1] + bj[1];
        o0.z = acc[i][2] + bj[2]; o0.w = acc[i][3] + bj[3];
        o1.x = acc[i][4] + bj[4]; o1.y = acc[i][5] + bj[5];
        o1.z = acc[i][6] + bj[6]; o1.w = acc[i][7] + bj[7];
        *(float4*)&C[(size_t)m * N + n0 + tx * 8]     = o0;
        *(float4*)&C[(size_t)m * N + n0 + tx * 8 + 4] = o1;
    }
}

// ---------------------------------------------------------------------------
// Flash attention: one CTA per (q-block of 64 rows, head, batch).
// smem tiles 64x64 (pad to 68). 256 threads as 16x16, 4x4 per thread.
// Scale folded into Q at load. Online softmax, shuffle reduce over 16 lanes.
// ---------------------------------------------------------------------------
#define APAD 68
#define ATILE (64 * APAD)

__global__ __launch_bounds__(256) void attn_kernel(
    const float* __restrict__ Q, const float* __restrict__ K,
    const float* __restrict__ V, float* __restrict__ O)
{
    extern __shared__ float smem[];
    float (*Qs)[APAD] = (float(*)[APAD])(smem);              // Qs[dk][r]
    float (*Ks)[APAD] = (float(*)[APAD])(smem + ATILE);      // Ks[dk][c]
    float (*Vs)[APAD] = (float(*)[APAD])(smem + 2 * ATILE);  // Vs[key][dk]
    float (*Ps)[APAD] = (float(*)[APAD])(smem + 3 * ATILE);  // Ps[key][r]

    const int tid = threadIdx.x;
    const int q0  = blockIdx.x * 64;
    const int h   = blockIdx.y;
    const int b   = blockIdx.z;

    const float* Qb = Q + (size_t)b * NSEQ * DMODEL + h * DKH;
    const float* Kb = K + (size_t)b * NSEQ * DMODEL + h * DKH;
    const float* Vb = V + (size_t)b * NSEQ * DMODEL + h * DKH;
    float*       Ob = O + (size_t)b * NSEQ * DMODEL + h * DKH;

    const int ty = tid >> 4;   // 0..15 -> rows ty*4..+3
    const int tx = tid & 15;   // 0..15 -> cols tx*4..+3

    // Load Q tile transposed, pre-scaled by DK^-0.5 = 0.125
#pragma unroll
    for (int i = 0; i < 4; ++i) {
        int idx = tid + i * 256;
        int row = idx >> 4;           // 0..63
        int kg  = (idx & 15) << 2;    // 0..60 step 4
        float4 qv = *(const float4*)&Qb[(size_t)(q0 + row) * DMODEL + kg];
        Qs[kg + 0][row] = qv.x * 0.125f;
        Qs[kg + 1][row] = qv.y * 0.125f;
        Qs[kg + 2][row] = qv.z * 0.125f;
        Qs[kg + 3][row] = qv.w * 0.125f;
    }

    float m_i[4], l_i[4], Oacc[4][4];
#pragma unroll
    for (int i = 0; i < 4; ++i) {
        m_i[i] = -INFINITY; l_i[i] = 0.f;
#pragma unroll
        for (int j = 0; j < 4; ++j) Oacc[i][j] = 0.f;
    }

    for (int k0 = 0; k0 < NSEQ; k0 += 64) {
        __syncthreads();   // prior PV reads (and Q load on first iter) done
        // Load K (transposed) and V (natural)
#pragma unroll
        for (int i = 0; i < 4; ++i) {
            int idx = tid + i * 256;
            int row = idx >> 4;
            int kg  = (idx & 15) << 2;
            float4 kv = *(const float4*)&Kb[(size_t)(k0 + row) * DMODEL + kg];
            Ks[kg + 0][row] = kv.x; Ks[kg + 1][row] = kv.y;
            Ks[kg + 2][row] = kv.z; Ks[kg + 3][row] = kv.w;
            float4 vv = *(const float4*)&Vb[(size_t)(k0 + row) * DMODEL + kg];
            *(float4*)&Vs[row][kg] = vv;
        }
        __syncthreads();

        // S = (Q * scale) @ K^T, 4x4 per thread
        float s[4][4] = {{0.f,0.f,0.f,0.f},{0.f,0.f,0.f,0.f},
                         {0.f,0.f,0.f,0.f},{0.f,0.f,0.f,0.f}};
#pragma unroll 8
        for (int dk = 0; dk < 64; ++dk) {
            float4 qa = *(const float4*)&Qs[dk][ty * 4];
            float4 kb = *(const float4*)&Ks[dk][tx * 4];
            float ar[4] = {qa.x, qa.y, qa.z, qa.w};
            float br[4] = {kb.x, kb.y, kb.z, kb.w};
#pragma unroll
            for (int i = 0; i < 4; ++i)
#pragma unroll
                for (int j = 0; j < 4; ++j)
                    s[i][j] = fmaf(ar[i], br[j], s[i][j]);
        }

        // Online softmax per row (reduce over the 16 tx lanes)
#pragma unroll
        for (int i = 0; i < 4; ++i) {
            float mx = fmaxf(fmaxf(s[i][0], s[i][1]), fmaxf(s[i][2], s[i][3]));
#pragma unroll
            for (int o = 8; o >= 1; o >>= 1)
                mx = fmaxf(mx, __shfl_xor_sync(0xffffffffu, mx, o));
            float mn = fmaxf(m_i[i], mx);
            float corr = __expf(m_i[i] - mn);
            m_i[i] = mn;
            float rs = 0.f;
#pragma unroll
            for (int j = 0; j < 4; ++j) {
                float p = __expf(s[i][j] - mn);
                s[i][j] = p;
                rs += p;
            }
#pragma unroll
            for (int o = 8; o >= 1; o >>= 1)
                rs += __shfl_xor_sync(0xffffffffu, rs, o);
            l_i[i] = l_i[i] * corr + rs;
#pragma unroll
            for (int j = 0; j < 4; ++j) Oacc[i][j] *= corr;
        }

        // Store P transposed: Ps[key][row]
#pragma unroll
        for (int i = 0; i < 4; ++i)
#pragma unroll
            for (int j = 0; j < 4; ++j)
                Ps[tx * 4 + j][ty * 4 + i] = s[i][j];
        __syncthreads();

        // O += P @ V
#pragma unroll 8
        for (int k = 0; k < 64; ++k) {
            float4 p4 = *(const float4*)&Ps[k][ty * 4];
            float4 v4 = *(const float4*)&Vs[k][tx * 4];
            float pr[4] = {p4.x, p4.y, p4.z, p4.w};
            float vr[4] = {v4.x, v4.y, v4.z, v4.w};
#pragma unroll
            for (int i = 0; i < 4; ++i)
#pragma unroll
                for (int j = 0; j < 4; ++j)
                    Oacc[i][j] = fmaf(pr[i], vr[j], Oacc[i][j]);
        }
    }

    // Normalize and write out (row stride DMODEL keeps head-merge implicit)
#pragma unroll
    for (int i = 0; i < 4; ++i) {
        float inv = 1.f / l_i[i];
        float4 o;
        o.x = Oacc[i][0] * inv; o.y = Oacc[i][1] * inv;
        o.z = Oacc[i][2] * inv; o.w = Oacc[i][3] * inv;
        *(float4*)&Ob[(size_t)(q0 + ty * 4 + i) * DMODEL + tx * 4] = o;
    }
}

// ---------------------------------------------------------------------------
extern "C" void kernel_launch(void* const* d_in, const int* in_sizes, int n_in,
                              void* d_out, int out_size)
{
    const float* q  = (const float*)d_in[0];
    const float* k  = (const float*)d_in[1];
    const float* v  = (const float*)d_in[2];
    const float* Wq = (const float*)d_in[3];
    const float* bq = (const float*)d_in[4];
    const float* Wk = (const float*)d_in[5];
    const float* bk = (const float*)d_in[6];
    const float* Wv = (const float*)d_in[7];
    const float* bv = (const float*)d_in[8];
    const float* Wo = (const float*)d_in[9];
    const float* bo = (const float*)d_in[10];
    float* out = (float*)d_out;

    float *gq, *gk, *gv, *go;
    cudaGetSymbolAddress((void**)&gq, g_q);
    cudaGetSymbolAddress((void**)&gk, g_k);
    cudaGetSymbolAddress((void**)&gv, g_v);
    cudaGetSymbolAddress((void**)&go, g_o);

    dim3 ggrid(DMODEL / 128, MROWS / 128);   // (8, 32)

    sgemm_nt_bias<<<ggrid, 256>>>(q, Wq, bq, gq, MROWS, DMODEL, DMODEL);
    sgemm_nt_bias<<<ggrid, 256>>>(k, Wk, bk, gk, MROWS, DMODEL, DMODEL);
    sgemm_nt_bias<<<ggrid, 256>>>(v, Wv, bv, gv, MROWS, DMODEL, DMODEL);

    const int smem_bytes = 4 * ATILE * (int)sizeof(float);  // 69632
    cudaFuncSetAttribute(attn_kernel,
                         cudaFuncAttributeMaxDynamicSharedMemorySize, smem_bytes);
    dim3 agrid(NSEQ / 64, NHEAD, BSZ);       // (32, 16, 2)
    attn_kernel<<<agrid, 256, smem_bytes>>>(gq, gk, gv, go);

    sgemm_nt_bias<<<ggrid, 256>>>(go, Wo, bo, out, MROWS, DMODEL, DMODEL);
}

// round 5
// speedup vs baseline: 1.0578x; 1.0578x over previous
#include <cuda_runtime.h>
#include <math.h>

#define BSZ    2
#define NSEQ   2048
#define DMODEL 1024
#define NHEAD  16
#define DKH    64
#define MROWS  (BSZ * NSEQ)     // 4096

// Scratch (allocation-free rule: __device__ globals)
__device__ float g_q[BSZ * NSEQ * DMODEL];
__device__ float g_k[BSZ * NSEQ * DMODEL];
__device__ float g_v[BSZ * NSEQ * DMODEL];
__device__ float g_o[BSZ * NSEQ * DMODEL];

// ---------------------------------------------------------------------------
// SGEMM (NT): C[m][n] = sum_k A[m][k] * W[n][k] + bias[n]
// A: [M,K] row-major, W: [N,K] row-major. 128x128 tile, K-step 16, 256 thr, 8x8.
// ---------------------------------------------------------------------------
__global__ __launch_bounds__(256) void sgemm_nt_bias(
    const float* __restrict__ A, const float* __restrict__ W,
    const float* __restrict__ bias, float* __restrict__ C,
    int M, int N, int K)
{
    __shared__ float As[16][132];   // As[k][m]
    __shared__ float Ws[16][132];   // Ws[k][n]

    const int tid = threadIdx.x;
    const int m0 = blockIdx.y * 128;
    const int n0 = blockIdx.x * 128;
    const int ty = tid >> 4;
    const int tx = tid & 15;

    float acc[8][8];
#pragma unroll
    for (int i = 0; i < 8; ++i)
#pragma unroll
        for (int j = 0; j < 8; ++j) acc[i][j] = 0.f;

    for (int kt = 0; kt < K; kt += 16) {
        float4 av[2], wv[2];
#pragma unroll
        for (int i = 0; i < 2; ++i) {
            int idx = tid + i * 256;
            int row = idx >> 2;
            int kg  = (idx & 3) << 2;
            av[i] = *(const float4*)&A[(size_t)(m0 + row) * K + kt + kg];
            wv[i] = *(const float4*)&W[(size_t)(n0 + row) * K + kt + kg];
        }
        __syncthreads();
#pragma unroll
        for (int i = 0; i < 2; ++i) {
            int idx = tid + i * 256;
            int row = idx >> 2;
            int kg  = (idx & 3) << 2;
            As[kg + 0][row] = av[i].x; As[kg + 1][row] = av[i].y;
            As[kg + 2][row] = av[i].z; As[kg + 3][row] = av[i].w;
            Ws[kg + 0][row] = wv[i].x; Ws[kg + 1][row] = wv[i].y;
            Ws[kg + 2][row] = wv[i].z; Ws[kg + 3][row] = wv[i].w;
        }
        __syncthreads();

#pragma unroll
        for (int kk = 0; kk < 16; ++kk) {
            float4 a0 = *(const float4*)&As[kk][ty * 8];
            float4 a1 = *(const float4*)&As[kk][ty * 8 + 4];
            float4 b0 = *(const float4*)&Ws[kk][tx * 8];
            float4 b1 = *(const float4*)&Ws[kk][tx * 8 + 4];
            float ar[8] = {a0.x, a0.y, a0.z, a0.w, a1.x, a1.y, a1.z, a1.w};
            float br[8] = {b0.x, b0.y, b0.z, b0.w, b1.x, b1.y, b1.z, b1.w};
#pragma unroll
            for (int i = 0; i < 8; ++i)
#pragma unroll
                for (int j = 0; j < 8; ++j)
                    acc[i][j] = fmaf(ar[i], br[j], acc[i][j]);
        }
    }

    float bj[8];
#pragma unroll
    for (int j = 0; j < 8; ++j) bj[j] = bias[n0 + tx * 8 + j];

#pragma unroll
    for (int i = 0; i < 8; ++i) {
        int m = m0 + ty * 8 + i;
        float4 o0, o1;
        o0.x = acc[i][0] + bj[0]; o0.y = acc[i][1] + bj[1];
        o0.z = acc[i][2] + bj[2]; o0.w = acc[i][3] + bj[3];
        o1.x = acc[i][4] + bj[4]; o1.y = acc[i][5] + bj[5];
        o1.z = acc[i][6] + bj[6]; o1.w = acc[i][7] + bj[7];
        *(float4*)&C[(size_t)m * N + n0 + tx * 8]     = o0;
        *(float4*)&C[(size_t)m * N + n0 + tx * 8 + 4] = o1;
    }
}

// ---------------------------------------------------------------------------
// Flash attention v2: one CTA per (128-row q-block, head, batch).
// 256 threads as 16x16; per thread 8 q-rows x 4 (keys / dk cols).
// Layouts chosen for conflict-free smem traffic:
//   Qs[dk][row]  (transposed once per CTA; broadcast float4 reads)
//   Ks[dk][col]  (transposed per tile; conflict-free float4 reads in S loop)
//   Vs[key][dk]  (natural; conflict-free float4 reads)
//   Ps[row][key] (row-major -> per-thread float4 STORES are conflict-free,
//                 PV reads P via broadcast float4 over 4-key blocks)
// ---------------------------------------------------------------------------
#define QPITCH 132
#define KPITCH 68
#define QS_OFF 0
#define KS_OFF (64 * QPITCH)                 // 8448
#define VS_OFF (KS_OFF + 64 * KPITCH)        // 12800
#define PS_OFF (VS_OFF + 64 * KPITCH)        // 17152
#define SMEM_FLOATS (PS_OFF + 128 * KPITCH)  // 25856 -> 103424 B

__global__ __launch_bounds__(256, 2) void attn_kernel(
    const float* __restrict__ Q, const float* __restrict__ K,
    const float* __restrict__ V, float* __restrict__ O)
{
    extern __shared__ float smem[];
    float (*Qs)[QPITCH] = (float(*)[QPITCH])(smem + QS_OFF);
    float (*Ks)[KPITCH] = (float(*)[KPITCH])(smem + KS_OFF);
    float (*Vs)[KPITCH] = (float(*)[KPITCH])(smem + VS_OFF);
    float (*Ps)[KPITCH] = (float(*)[KPITCH])(smem + PS_OFF);

    const int tid = threadIdx.x;
    const int q0  = blockIdx.x * 128;
    const int h   = blockIdx.y;
    const int b   = blockIdx.z;

    const float* Qb = Q + (size_t)b * NSEQ * DMODEL + h * DKH;
    const float* Kb = K + (size_t)b * NSEQ * DMODEL + h * DKH;
    const float* Vb = V + (size_t)b * NSEQ * DMODEL + h * DKH;
    float*       Ob = O + (size_t)b * NSEQ * DMODEL + h * DKH;

    const int ty = tid >> 4;   // 0..15 -> q-rows ty*8..+7
    const int tx = tid & 15;   // 0..15 -> cols tx*4..+3

    // Load Q tile (128 x 64) transposed, pre-scaled by DK^-0.5 = 0.125
#pragma unroll
    for (int i = 0; i < 8; ++i) {
        int idx = tid + i * 256;          // 0..2047
        int row = idx >> 4;               // 0..127
        int kg  = (idx & 15) << 2;        // 0..60
        float4 qv = *(const float4*)&Qb[(size_t)(q0 + row) * DMODEL + kg];
        Qs[kg + 0][row] = qv.x * 0.125f;
        Qs[kg + 1][row] = qv.y * 0.125f;
        Qs[kg + 2][row] = qv.z * 0.125f;
        Qs[kg + 3][row] = qv.w * 0.125f;
    }

    float m_i[8], l_i[8], Oacc[8][4];
#pragma unroll
    for (int i = 0; i < 8; ++i) {
        m_i[i] = -INFINITY; l_i[i] = 0.f;
#pragma unroll
        for (int j = 0; j < 4; ++j) Oacc[i][j] = 0.f;
    }

    for (int k0 = 0; k0 < NSEQ; k0 += 64) {
        __syncthreads();   // prior PV reads of Ps/Vs done (Q load on iter 0)
#pragma unroll
        for (int i = 0; i < 4; ++i) {
            int idx = tid + i * 256;      // 0..1023
            int row = idx >> 4;           // 0..63
            int kg  = (idx & 15) << 2;
            float4 kv = *(const float4*)&Kb[(size_t)(k0 + row) * DMODEL + kg];
            Ks[kg + 0][row] = kv.x; Ks[kg + 1][row] = kv.y;
            Ks[kg + 2][row] = kv.z; Ks[kg + 3][row] = kv.w;
            float4 vv = *(const float4*)&Vb[(size_t)(k0 + row) * DMODEL + kg];
            *(float4*)&Vs[row][kg] = vv;
        }
        __syncthreads();

        // S = (Q*scale) @ K^T : 8x4 per thread
        float s[8][4];
#pragma unroll
        for (int i = 0; i < 8; ++i)
#pragma unroll
            for (int j = 0; j < 4; ++j) s[i][j] = 0.f;

#pragma unroll 8
        for (int dk = 0; dk < 64; ++dk) {
            float4 qa0 = *(const float4*)&Qs[dk][ty * 8];
            float4 qa1 = *(const float4*)&Qs[dk][ty * 8 + 4];
            float4 kb4 = *(const float4*)&Ks[dk][tx * 4];
            float ar[8] = {qa0.x, qa0.y, qa0.z, qa0.w,
                           qa1.x, qa1.y, qa1.z, qa1.w};
            float br[4] = {kb4.x, kb4.y, kb4.z, kb4.w};
#pragma unroll
            for (int i = 0; i < 8; ++i)
#pragma unroll
                for (int j = 0; j < 4; ++j)
                    s[i][j] = fmaf(ar[i], br[j], s[i][j]);
        }

        // Online softmax per row (reduce over the 16 tx lanes)
#pragma unroll
        for (int i = 0; i < 8; ++i) {
            float mx = fmaxf(fmaxf(s[i][0], s[i][1]), fmaxf(s[i][2], s[i][3]));
#pragma unroll
            for (int o = 8; o >= 1; o >>= 1)
                mx = fmaxf(mx, __shfl_xor_sync(0xffffffffu, mx, o));
            float mn = fmaxf(m_i[i], mx);
            float corr = __expf(m_i[i] - mn);
            m_i[i] = mn;
            float rs = 0.f;
#pragma unroll
            for (int j = 0; j < 4; ++j) {
                float p = __expf(s[i][j] - mn);
                s[i][j] = p;
                rs += p;
            }
#pragma unroll
            for (int o = 8; o >= 1; o >>= 1)
                rs += __shfl_xor_sync(0xffffffffu, rs, o);
            l_i[i] = l_i[i] * corr + rs;
#pragma unroll
            for (int j = 0; j < 4; ++j) Oacc[i][j] *= corr;
        }

        // Store P row-major: conflict-free float4 stores
#pragma unroll
        for (int i = 0; i < 8; ++i) {
            float4 p4;
            p4.x = s[i][0]; p4.y = s[i][1]; p4.z = s[i][2]; p4.w = s[i][3];
            *(float4*)&Ps[ty * 8 + i][tx * 4] = p4;
        }
        __syncthreads();

        // O += P @ V over 4-key blocks
#pragma unroll 2
        for (int kb = 0; kb < 64; kb += 4) {
            float4 v0 = *(const float4*)&Vs[kb + 0][tx * 4];
            float4 v1 = *(const float4*)&Vs[kb + 1][tx * 4];
            float4 v2 = *(const float4*)&Vs[kb + 2][tx * 4];
            float4 v3 = *(const float4*)&Vs[kb + 3][tx * 4];
#pragma unroll
            for (int i = 0; i < 8; ++i) {
                float4 pp = *(const float4*)&Ps[ty * 8 + i][kb];
                Oacc[i][0] = fmaf(pp.x, v0.x, Oacc[i][0]);
                Oacc[i][1] = fmaf(pp.x, v0.y, Oacc[i][1]);
                Oacc[i][2] = fmaf(pp.x, v0.z, Oacc[i][2]);
                Oacc[i][3] = fmaf(pp.x, v0.w, Oacc[i][3]);
                Oacc[i][0] = fmaf(pp.y, v1.x, Oacc[i][0]);
                Oacc[i][1] = fmaf(pp.y, v1.y, Oacc[i][1]);
                Oacc[i][2] = fmaf(pp.y, v1.z, Oacc[i][2]);
                Oacc[i][3] = fmaf(pp.y, v1.w, Oacc[i][3]);
                Oacc[i][0] = fmaf(pp.z, v2.x, Oacc[i][0]);
                Oacc[i][1] = fmaf(pp.z, v2.y, Oacc[i][1]);
                Oacc[i][2] = fmaf(pp.z, v2.z, Oacc[i][2]);
                Oacc[i][3] = fmaf(pp.z, v2.w, Oacc[i][3]);
                Oacc[i][0] = fmaf(pp.w, v3.x, Oacc[i][0]);
                Oacc[i][1] = fmaf(pp.w, v3.y, Oacc[i][1]);
                Oacc[i][2] = fmaf(pp.w, v3.z, Oacc[i][2]);
                Oacc[i][3] = fmaf(pp.w, v3.w, Oacc[i][3]);
            }
        }
    }

    // Normalize and write out (row stride DMODEL keeps head-merge implicit)
#pragma unroll
    for (int i = 0; i < 8; ++i) {
        float inv = 1.f / l_i[i];
        float4 o;
        o.x = Oacc[i][0] * inv; o.y = Oacc[i][1] * inv;
        o.z = Oacc[i][2] * inv; o.w = Oacc[i][3] * inv;
        *(float4*)&Ob[(size_t)(q0 + ty * 8 + i) * DMODEL + tx * 4] = o;
    }
}

// ---------------------------------------------------------------------------
extern "C" void kernel_launch(void* const* d_in, const int* in_sizes, int n_in,
                              void* d_out, int out_size)
{
    const float* q  = (const float*)d_in[0];
    const float* k  = (const float*)d_in[1];
    const float* v  = (const float*)d_in[2];
    const float* Wq = (const float*)d_in[3];
    const float* bq = (const float*)d_in[4];
    const float* Wk = (const float*)d_in[5];
    const float* bk = (const float*)d_in[6];
    const float* Wv = (const float*)d_in[7];
    const float* bv = (const float*)d_in[8];
    const float* Wo = (const float*)d_in[9];
    const float* bo = (const float*)d_in[10];
    float* out = (float*)d_out;

    float *gq, *gk, *gv, *go;
    cudaGetSymbolAddress((void**)&gq, g_q);
    cudaGetSymbolAddress((void**)&gk, g_k);
    cudaGetSymbolAddress((void**)&gv, g_v);
    cudaGetSymbolAddress((void**)&go, g_o);

    dim3 ggrid(DMODEL / 128, MROWS / 128);   // (8, 32)

    sgemm_nt_bias<<<ggrid, 256>>>(q, Wq, bq, gq, MROWS, DMODEL, DMODEL);
    sgemm_nt_bias<<<ggrid, 256>>>(k, Wk, bk, gk, MROWS, DMODEL, DMODEL);
    sgemm_nt_bias<<<ggrid, 256>>>(v, Wv, bv, gv, MROWS, DMODEL, DMODEL);

    const int smem_bytes = SMEM_FLOATS * (int)sizeof(float);  // 103424
    cudaFuncSetAttribute(attn_kernel,
                         cudaFuncAttributeMaxDynamicSharedMemorySize, smem_bytes);
    dim3 agrid(NSEQ / 128, NHEAD, BSZ);      // (16, 16, 2)
    attn_kernel<<<agrid, 256, smem_bytes>>>(gq, gk, gv, go);

    sgemm_nt_bias<<<ggrid, 256>>>(go, Wo, bo, out, MROWS, DMODEL, DMODEL);
}